// round 1
// baseline (speedup 1.0000x reference)
#include <cuda_runtime.h>
#include <cuda_bf16.h>
#include <float.h>

#define BZ   64
#define SEQ  2048
#define DIM  2048
#define NE   16
#define RK   4
#define SCH  16              // s-chunks
#define SPER (SEQ / SCH)     // 128 rows per chunk

// Scratch: partial sums over SEQ chunks. [SCH][BZ][DIM] fp32 = 8 MB.
__device__ float g_part[SCH * BZ * DIM];

// ---------------------------------------------------------------------------
// Stage A: memory-bound streaming reduction of input_x over the SEQ axis.
// Grid (BZ, SCH), 512 threads; each thread owns 4 contiguous d's (float4).
// ---------------------------------------------------------------------------
__global__ __launch_bounds__(512) void stageA_reduce(const float* __restrict__ x) {
    const int b  = blockIdx.x;
    const int sc = blockIdx.y;
    const int t  = threadIdx.x;           // 0..511, covers DIM/4 = 512 float4 lanes

    const float4* __restrict__ xp =
        reinterpret_cast<const float4*>(x)
        + ((size_t)b * SEQ + (size_t)sc * SPER) * (DIM / 4) + t;

    float4 a0 = make_float4(0.f, 0.f, 0.f, 0.f);
    float4 a1 = a0, a2 = a0, a3 = a0;

    #pragma unroll 4
    for (int s = 0; s < SPER; s += 4) {
        float4 v0 = xp[(size_t)(s + 0) * (DIM / 4)];
        float4 v1 = xp[(size_t)(s + 1) * (DIM / 4)];
        float4 v2 = xp[(size_t)(s + 2) * (DIM / 4)];
        float4 v3 = xp[(size_t)(s + 3) * (DIM / 4)];
        a0.x += v0.x; a0.y += v0.y; a0.z += v0.z; a0.w += v0.w;
        a1.x += v1.x; a1.y += v1.y; a1.z += v1.z; a1.w += v1.w;
        a2.x += v2.x; a2.y += v2.y; a2.z += v2.z; a2.w += v2.w;
        a3.x += v3.x; a3.y += v3.y; a3.z += v3.z; a3.w += v3.w;
    }
    float4 r;
    r.x = (a0.x + a1.x) + (a2.x + a3.x);
    r.y = (a0.y + a1.y) + (a2.y + a3.y);
    r.z = (a0.z + a1.z) + (a2.z + a3.z);
    r.w = (a0.w + a1.w) + (a2.w + a3.w);

    float4* __restrict__ out =
        reinterpret_cast<float4*>(g_part) + ((size_t)sc * BZ + b) * (DIM / 4) + t;
    *out = r;
}

// ---------------------------------------------------------------------------
// Stage B: one block per batch row. Reduce partials, both 16-expert dots,
// softmax combine, top-4 (jax tie-break: strict >, descending), normalize.
// ---------------------------------------------------------------------------
__global__ __launch_bounds__(256) void stageB_finalize(
    const int*   __restrict__ idx,
    const float* __restrict__ W_b,
    const float* __restrict__ embed,
    const float* __restrict__ W_c,
    float*       __restrict__ out,
    int out_size)
{
    const int b    = blockIdx.x;
    const int t    = threadIdx.x;      // 256 threads
    const int lane = t & 31;
    const int warp = t >> 5;           // 8 warps

    const int i0 = idx[b * RK + 0];
    const int i1 = idx[b * RK + 1];
    const int i2 = idx[b * RK + 2];
    const int i3 = idx[b * RK + 3];

    float acc1[NE];
    float acc2[NE];
    #pragma unroll
    for (int e = 0; e < NE; e++) { acc1[e] = 0.f; acc2[e] = 0.f; }

    for (int d = t; d < DIM; d += 256) {
        float xs = 0.f;
        #pragma unroll
        for (int sc = 0; sc < SCH; sc++)
            xs += g_part[((size_t)sc * BZ + b) * DIM + d];
        const float xm  = xs * (1.0f / (float)SEQ);
        const float hid = 0.25f * (embed[(size_t)i0 * DIM + d] + embed[(size_t)i1 * DIM + d] +
                                   embed[(size_t)i2 * DIM + d] + embed[(size_t)i3 * DIM + d]);
        #pragma unroll
        for (int e = 0; e < NE; e++) {
            acc1[e] += xm  * W_b[(size_t)e * DIM + d];
            acc2[e] += hid * W_c[(size_t)e * DIM + d];
        }
    }

    // warp-level reduce all 32 accumulators
    #pragma unroll
    for (int e = 0; e < NE; e++) {
        #pragma unroll
        for (int off = 16; off > 0; off >>= 1) {
            acc1[e] += __shfl_down_sync(0xFFFFFFFFu, acc1[e], off);
            acc2[e] += __shfl_down_sync(0xFFFFFFFFu, acc2[e], off);
        }
    }

    __shared__ float s_red[8][2 * NE];
    if (lane == 0) {
        #pragma unroll
        for (int e = 0; e < NE; e++) {
            s_red[warp][e]      = acc1[e];
            s_red[warp][NE + e] = acc2[e];
        }
    }
    __syncthreads();

    __shared__ float s_log1[NE];
    __shared__ float s_log2[NE];
    if (t < 2 * NE) {
        float v = 0.f;
        #pragma unroll
        for (int w = 0; w < 8; w++) v += s_red[w][t];
        if (t < NE) s_log1[t] = v;
        else        s_log2[t - NE] = v;
    }
    __syncthreads();

    if (t == 0) {
        float sm1[NE], sm2[NE], logits[NE], score[NE];

        // softmax(logits1)
        float m1 = -FLT_MAX, m2 = -FLT_MAX;
        #pragma unroll
        for (int e = 0; e < NE; e++) { m1 = fmaxf(m1, s_log1[e]); m2 = fmaxf(m2, s_log2[e]); }
        float z1 = 0.f, z2 = 0.f;
        #pragma unroll
        for (int e = 0; e < NE; e++) {
            sm1[e] = __expf(s_log1[e] - m1); z1 += sm1[e];
            sm2[e] = __expf(s_log2[e] - m2); z2 += sm2[e];
        }
        const float iz1 = 1.f / z1, iz2 = 1.f / z2;
        float mC = -FLT_MAX;
        #pragma unroll
        for (int e = 0; e < NE; e++) {
            logits[e] = sm1[e] * iz1 + sm2[e] * iz2;   // IFS_WEIGHT = 1.0
            mC = fmaxf(mC, logits[e]);
        }

        // top-4 by selection: strict > keeps lowest index on ties; descending order
        int   topk[RK];
        bool  taken[NE];
        #pragma unroll
        for (int e = 0; e < NE; e++) taken[e] = false;
        #pragma unroll
        for (int r = 0; r < RK; r++) {
            float best = -FLT_MAX;
            int   bi   = 0;
            #pragma unroll
            for (int e = 0; e < NE; e++) {
                if (!taken[e] && logits[e] > best) { best = logits[e]; bi = e; }
            }
            taken[bi] = true;
            topk[r] = bi;
        }

        // score = softmax(logits); mask top-4; normalize
        float zC = 0.f;
        #pragma unroll
        for (int e = 0; e < NE; e++) { score[e] = __expf(logits[e] - mC); zC += score[e]; }
        const float izC = 1.f / zC;
        float denom = 0.f;
        #pragma unroll
        for (int e = 0; e < NE; e++) {
            score[e] *= izC;
            if (taken[e]) denom += score[e];
        }
        denom = fmaxf(denom, FLT_EPSILON);  // jnp.finfo(f32).eps clip
        const float inv_d = 1.f / denom;

        if (out_size >= BZ * NE) {
            #pragma unroll
            for (int e = 0; e < NE; e++)
                out[b * NE + e] = taken[e] ? score[e] * inv_d : 0.f;
        }
        if (out_size >= BZ * NE + BZ * RK) {
            #pragma unroll
            for (int r = 0; r < RK; r++)
                out[BZ * NE + b * RK + r] = (float)topk[r];
        }
    }
}

extern "C" void kernel_launch(void* const* d_in, const int* in_sizes, int n_in,
                              void* d_out, int out_size) {
    const float* x     = (const float*)d_in[0];
    const int*   idx   = (const int*)  d_in[1];
    const float* W_b   = (const float*)d_in[2];
    const float* embed = (const float*)d_in[3];
    const float* W_c   = (const float*)d_in[4];
    float* out = (float*)d_out;

    dim3 gA(BZ, SCH);
    stageA_reduce<<<gA, 512>>>(x);
    stageB_finalize<<<BZ, 256>>>(idx, W_b, embed, W_c, out, out_size);
}

// round 2
// speedup vs baseline: 1.1331x; 1.1331x over previous
#include <cuda_runtime.h>
#include <cuda_bf16.h>
#include <float.h>

#define BZ   64
#define SEQ  2048
#define DIM  2048
#define NE   16
#define RK   4
#define SCH  16              // s-chunks
#define SPER (SEQ / SCH)     // 128 rows per chunk

// Per-chunk partial logits1 (pre-mean): [SCH][BZ][NE] = 64 KB. Deterministic
// (no float atomics): stage B sums the SCH partials in a fixed order.
__device__ float g_p1[SCH * BZ * NE];

// ---------------------------------------------------------------------------
// Stage A: stream input_x (1.07 GB), reduce over SEQ chunk, and fold the
// W_b dot into the epilogue (W_b is L2-resident; 64 FMAs per 512 loads ~ free).
// Grid (BZ, SCH), 512 threads; thread t owns d = 4t..4t+3 (float4 lanes).
// ---------------------------------------------------------------------------
__global__ __launch_bounds__(512) void stageA_reduce(const float* __restrict__ x,
                                                     const float* __restrict__ W_b) {
    const int b    = blockIdx.x;
    const int sc   = blockIdx.y;
    const int t    = threadIdx.x;      // 0..511
    const int lane = t & 31;
    const int warp = t >> 5;           // 16 warps

    const float4* __restrict__ xp =
        reinterpret_cast<const float4*>(x)
        + ((size_t)b * SEQ + (size_t)sc * SPER) * (DIM / 4) + t;

    float4 a0 = make_float4(0.f, 0.f, 0.f, 0.f);
    float4 a1 = a0, a2 = a0, a3 = a0;

    #pragma unroll 4
    for (int s = 0; s < SPER; s += 4) {
        float4 v0 = xp[(size_t)(s + 0) * (DIM / 4)];
        float4 v1 = xp[(size_t)(s + 1) * (DIM / 4)];
        float4 v2 = xp[(size_t)(s + 2) * (DIM / 4)];
        float4 v3 = xp[(size_t)(s + 3) * (DIM / 4)];
        a0.x += v0.x; a0.y += v0.y; a0.z += v0.z; a0.w += v0.w;
        a1.x += v1.x; a1.y += v1.y; a1.z += v1.z; a1.w += v1.w;
        a2.x += v2.x; a2.y += v2.y; a2.z += v2.z; a2.w += v2.w;
        a3.x += v3.x; a3.y += v3.y; a3.z += v3.z; a3.w += v3.w;
    }
    float4 r;
    r.x = (a0.x + a1.x) + (a2.x + a3.x);
    r.y = (a0.y + a1.y) + (a2.y + a3.y);
    r.z = (a0.z + a1.z) + (a2.z + a3.z);
    r.w = (a0.w + a1.w) + (a2.w + a3.w);

    // Epilogue: partial dot of this chunk-sum with all 16 expert rows of W_b.
    const float4* __restrict__ wb4 = reinterpret_cast<const float4*>(W_b);
    float p[NE];
    #pragma unroll
    for (int e = 0; e < NE; e++) {
        float4 w = wb4[e * (DIM / 4) + t];
        p[e] = (r.x * w.x + r.y * w.y) + (r.z * w.z + r.w * w.w);
    }

    // warp reduce the 16 partials
    #pragma unroll
    for (int e = 0; e < NE; e++) {
        #pragma unroll
        for (int off = 16; off > 0; off >>= 1)
            p[e] += __shfl_down_sync(0xFFFFFFFFu, p[e], off);
    }

    __shared__ float s_red[16][NE];
    if (lane == 0) {
        #pragma unroll
        for (int e = 0; e < NE; e++) s_red[warp][e] = p[e];
    }
    __syncthreads();

    if (t < NE) {
        float v = 0.f;
        #pragma unroll
        for (int w = 0; w < 16; w++) v += s_red[w][t];
        g_p1[((size_t)sc * BZ + b) * NE + t] = v;
    }
}

// ---------------------------------------------------------------------------
// Stage B: one block per batch row. Tiny now: embed-mean dot W_c (L2-hit),
// sum the SCH logits1 partials, softmax combine, top-4, normalize.
// ---------------------------------------------------------------------------
__global__ __launch_bounds__(512) void stageB_finalize(
    const int*   __restrict__ idx,
    const float* __restrict__ embed,
    const float* __restrict__ W_c,
    float*       __restrict__ out,
    int out_size)
{
    const int b    = blockIdx.x;
    const int t    = threadIdx.x;      // 512 threads
    const int lane = t & 31;
    const int warp = t >> 5;           // 16 warps

    const int i0 = idx[b * RK + 0];
    const int i1 = idx[b * RK + 1];
    const int i2 = idx[b * RK + 2];
    const int i3 = idx[b * RK + 3];

    float acc2[NE];
    #pragma unroll
    for (int e = 0; e < NE; e++) acc2[e] = 0.f;

    #pragma unroll
    for (int k = 0; k < DIM / 512; k++) {
        const int d = t + k * 512;
        const float hid = 0.25f * ((embed[(size_t)i0 * DIM + d] + embed[(size_t)i1 * DIM + d]) +
                                   (embed[(size_t)i2 * DIM + d] + embed[(size_t)i3 * DIM + d]));
        #pragma unroll
        for (int e = 0; e < NE; e++)
            acc2[e] += hid * W_c[(size_t)e * DIM + d];
    }

    #pragma unroll
    for (int e = 0; e < NE; e++) {
        #pragma unroll
        for (int off = 16; off > 0; off >>= 1)
            acc2[e] += __shfl_down_sync(0xFFFFFFFFu, acc2[e], off);
    }

    __shared__ float s_red[16][NE];
    __shared__ float s_log1[NE];
    __shared__ float s_log2[NE];
    if (lane == 0) {
        #pragma unroll
        for (int e = 0; e < NE; e++) s_red[warp][e] = acc2[e];
    }
    __syncthreads();

    if (t < NE) {
        float v = 0.f;
        #pragma unroll
        for (int w = 0; w < 16; w++) v += s_red[w][t];
        s_log2[t] = v;
        // logits1: deterministic fixed-order sum of SCH chunk partials, / SEQ
        float l1 = 0.f;
        #pragma unroll
        for (int sc = 0; sc < SCH; sc++)
            l1 += g_p1[((size_t)sc * BZ + b) * NE + t];
        s_log1[t] = l1 * (1.0f / (float)SEQ);
    }
    __syncthreads();

    if (t == 0) {
        float sm1[NE], sm2[NE], logits[NE], score[NE];

        float m1 = -FLT_MAX, m2 = -FLT_MAX;
        #pragma unroll
        for (int e = 0; e < NE; e++) { m1 = fmaxf(m1, s_log1[e]); m2 = fmaxf(m2, s_log2[e]); }
        float z1 = 0.f, z2 = 0.f;
        #pragma unroll
        for (int e = 0; e < NE; e++) {
            sm1[e] = __expf(s_log1[e] - m1); z1 += sm1[e];
            sm2[e] = __expf(s_log2[e] - m2); z2 += sm2[e];
        }
        const float iz1 = 1.f / z1, iz2 = 1.f / z2;
        float mC = -FLT_MAX;
        #pragma unroll
        for (int e = 0; e < NE; e++) {
            logits[e] = sm1[e] * iz1 + sm2[e] * iz2;   // IFS_WEIGHT = 1.0
            mC = fmaxf(mC, logits[e]);
        }

        // top-4 selection: strict > keeps lowest index on ties; descending order
        int  topk[RK];
        bool taken[NE];
        #pragma unroll
        for (int e = 0; e < NE; e++) taken[e] = false;
        #pragma unroll
        for (int r = 0; r < RK; r++) {
            float best = -FLT_MAX;
            int   bi   = 0;
            #pragma unroll
            for (int e = 0; e < NE; e++)
                if (!taken[e] && logits[e] > best) { best = logits[e]; bi = e; }
            taken[bi] = true;
            topk[r] = bi;
        }

        float zC = 0.f;
        #pragma unroll
        for (int e = 0; e < NE; e++) { score[e] = __expf(logits[e] - mC); zC += score[e]; }
        const float izC = 1.f / zC;
        float denom = 0.f;
        #pragma unroll
        for (int e = 0; e < NE; e++) {
            score[e] *= izC;
            if (taken[e]) denom += score[e];
        }
        denom = fmaxf(denom, FLT_EPSILON);
        const float inv_d = 1.f / denom;

        if (out_size >= BZ * NE) {
            #pragma unroll
            for (int e = 0; e < NE; e++)
                out[b * NE + e] = taken[e] ? score[e] * inv_d : 0.f;
        }
        if (out_size >= BZ * NE + BZ * RK) {
            #pragma unroll
            for (int r = 0; r < RK; r++)
                out[BZ * NE + b * RK + r] = (float)topk[r];
        }
    }
}

extern "C" void kernel_launch(void* const* d_in, const int* in_sizes, int n_in,
                              void* d_out, int out_size) {
    const float* x     = (const float*)d_in[0];
    const int*   idx   = (const int*)  d_in[1];
    const float* W_b   = (const float*)d_in[2];
    const float* embed = (const float*)d_in[3];
    const float* W_c   = (const float*)d_in[4];
    float* out = (float*)d_out;

    dim3 gA(BZ, SCH);
    stageA_reduce<<<gA, 512>>>(x, W_b);
    stageB_finalize<<<BZ, 512>>>(idx, embed, W_c, out, out_size);
}

// round 3
// speedup vs baseline: 1.1358x; 1.0024x over previous
#include <cuda_runtime.h>
#include <cuda_bf16.h>
#include <float.h>

#define BZ    64
#define SEQ   2048
#define DIM   2048
#define NE    16
#define RK    4
#define DCH   4                 // DIM chunks (blocks in y)
#define LANES (DIM / DCH / 4)   // 128 float4 lanes per block
#define RG    4                 // row-groups per block (512 thr / 128 lanes)
#define RPG   (SEQ / RG)        // 512 rows per row-group

// Partial logits per (dc, b, e). Summed in fixed order by the finalizer.
__device__ float g_p1[DCH * BZ * NE];
__device__ float g_p2[DCH * BZ * NE];
__device__ int   g_count;       // zero-init; last block resets to 0 each run

__global__ __launch_bounds__(512) void fused_selector(
    const float* __restrict__ x,
    const int*   __restrict__ idx,
    const float* __restrict__ W_b,
    const float* __restrict__ embed,
    const float* __restrict__ W_c,
    float*       __restrict__ out,
    int out_size)
{
    const int b    = blockIdx.x;
    const int dc   = blockIdx.y;
    const int t    = threadIdx.x;         // 0..511
    const int l    = t & (LANES - 1);     // float4 lane within slice
    const int g    = t >> 7;              // row-group 0..3
    const int lane = t & 31;
    const int warp = t >> 5;              // 16 warps

    const int dbase4 = dc * LANES;        // float4 offset of slice within a row

    // ---- main streaming loop: sum x[b, g*RPG..(g+1)*RPG, slice] ----
    const float4* __restrict__ xp =
        reinterpret_cast<const float4*>(x)
        + ((size_t)b * SEQ + (size_t)g * RPG) * (DIM / 4) + dbase4 + l;

    float4 a0 = make_float4(0.f, 0.f, 0.f, 0.f);
    float4 a1 = a0, a2 = a0, a3 = a0;

    #pragma unroll 4
    for (int s = 0; s < RPG; s += 4) {
        float4 v0 = xp[(size_t)(s + 0) * (DIM / 4)];
        float4 v1 = xp[(size_t)(s + 1) * (DIM / 4)];
        float4 v2 = xp[(size_t)(s + 2) * (DIM / 4)];
        float4 v3 = xp[(size_t)(s + 3) * (DIM / 4)];
        a0.x += v0.x; a0.y += v0.y; a0.z += v0.z; a0.w += v0.w;
        a1.x += v1.x; a1.y += v1.y; a1.z += v1.z; a1.w += v1.w;
        a2.x += v2.x; a2.y += v2.y; a2.z += v2.z; a2.w += v2.w;
        a3.x += v3.x; a3.y += v3.y; a3.z += v3.z; a3.w += v3.w;
    }
    float4 r;
    r.x = (a0.x + a1.x) + (a2.x + a3.x);
    r.y = (a0.y + a1.y) + (a2.y + a3.y);
    r.z = (a0.z + a1.z) + (a2.z + a3.z);
    r.w = (a0.w + a1.w) + (a2.w + a3.w);

    // ---- epilogue: W_b dot on this slice (L1 absorbs intra-block reuse) ----
    const float4* __restrict__ wb4 = reinterpret_cast<const float4*>(W_b);
    float p1[NE];
    #pragma unroll
    for (int e = 0; e < NE; e++) {
        float4 w = wb4[(size_t)e * (DIM / 4) + dbase4 + l];
        p1[e] = (r.x * w.x + r.y * w.y) + (r.z * w.z + r.w * w.w);
    }

    // ---- embed-mean dot W_c on this slice (row-group 0 only) ----
    float p2[NE];
    #pragma unroll
    for (int e = 0; e < NE; e++) p2[e] = 0.f;
    if (g == 0) {
        const int i0 = idx[b * RK + 0];
        const int i1 = idx[b * RK + 1];
        const int i2 = idx[b * RK + 2];
        const int i3 = idx[b * RK + 3];
        const float4* __restrict__ em4 = reinterpret_cast<const float4*>(embed);
        const float4* __restrict__ wc4 = reinterpret_cast<const float4*>(W_c);
        float4 e0 = em4[(size_t)i0 * (DIM / 4) + dbase4 + l];
        float4 e1 = em4[(size_t)i1 * (DIM / 4) + dbase4 + l];
        float4 e2 = em4[(size_t)i2 * (DIM / 4) + dbase4 + l];
        float4 e3 = em4[(size_t)i3 * (DIM / 4) + dbase4 + l];
        float4 h;
        h.x = 0.25f * ((e0.x + e1.x) + (e2.x + e3.x));
        h.y = 0.25f * ((e0.y + e1.y) + (e2.y + e3.y));
        h.z = 0.25f * ((e0.z + e1.z) + (e2.z + e3.z));
        h.w = 0.25f * ((e0.w + e1.w) + (e2.w + e3.w));
        #pragma unroll
        for (int e = 0; e < NE; e++) {
            float4 w = wc4[(size_t)e * (DIM / 4) + dbase4 + l];
            p2[e] = (h.x * w.x + h.y * w.y) + (h.z * w.z + h.w * w.w);
        }
    }

    // ---- warp reduce ----
    #pragma unroll
    for (int e = 0; e < NE; e++) {
        #pragma unroll
        for (int off = 16; off > 0; off >>= 1) {
            p1[e] += __shfl_down_sync(0xFFFFFFFFu, p1[e], off);
            if (warp < RG) p2[e] += __shfl_down_sync(0xFFFFFFFFu, p2[e], off);
        }
    }

    __shared__ float s1[16][NE];
    __shared__ float s2[RG][NE];
    __shared__ int   s_amLast;
    if (lane == 0) {
        #pragma unroll
        for (int e = 0; e < NE; e++) s1[warp][e] = p1[e];
        if (warp < RG) {
            #pragma unroll
            for (int e = 0; e < NE; e++) s2[warp][e] = p2[e];
        }
    }
    __syncthreads();

    if (t < NE) {
        float v1 = 0.f;
        #pragma unroll
        for (int w = 0; w < 16; w++) v1 += s1[w][t];
        g_p1[((size_t)dc * BZ + b) * NE + t] = v1;
        float v2 = 0.f;
        #pragma unroll
        for (int w = 0; w < RG; w++) v2 += s2[w][t];
        g_p2[((size_t)dc * BZ + b) * NE + t] = v2;
        __threadfence();
    }
    __syncthreads();

    if (t == 0) {
        int ticket = atomicAdd(&g_count, 1);
        s_amLast = (ticket == (int)(gridDim.x * gridDim.y) - 1);
    }
    __syncthreads();
    if (!s_amLast) return;
    __threadfence();  // acquire: see all blocks' g_p writes

    // ---- finalize: one thread per batch row ----
    if (t < BZ) {
        const int bb = t;
        float l1[NE], l2[NE];
        #pragma unroll
        for (int e = 0; e < NE; e++) {
            float v1 = 0.f, v2 = 0.f;
            #pragma unroll
            for (int d = 0; d < DCH; d++) {
                v1 += g_p1[((size_t)d * BZ + bb) * NE + e];
                v2 += g_p2[((size_t)d * BZ + bb) * NE + e];
            }
            l1[e] = v1 * (1.0f / (float)SEQ);
            l2[e] = v2;
        }

        float m1 = -FLT_MAX, m2 = -FLT_MAX;
        #pragma unroll
        for (int e = 0; e < NE; e++) { m1 = fmaxf(m1, l1[e]); m2 = fmaxf(m2, l2[e]); }
        float z1 = 0.f, z2 = 0.f;
        float sm1[NE], sm2[NE];
        #pragma unroll
        for (int e = 0; e < NE; e++) {
            sm1[e] = __expf(l1[e] - m1); z1 += sm1[e];
            sm2[e] = __expf(l2[e] - m2); z2 += sm2[e];
        }
        const float iz1 = 1.f / z1, iz2 = 1.f / z2;
        float logits[NE], score[NE];
        float mC = -FLT_MAX;
        #pragma unroll
        for (int e = 0; e < NE; e++) {
            logits[e] = sm1[e] * iz1 + sm2[e] * iz2;  // IFS_WEIGHT = 1.0
            mC = fmaxf(mC, logits[e]);
        }

        // top-4: strict > keeps lowest index on ties; descending order
        int  topk[RK];
        bool taken[NE];
        #pragma unroll
        for (int e = 0; e < NE; e++) taken[e] = false;
        #pragma unroll
        for (int r2 = 0; r2 < RK; r2++) {
            float best = -FLT_MAX;
            int   bi   = 0;
            #pragma unroll
            for (int e = 0; e < NE; e++)
                if (!taken[e] && logits[e] > best) { best = logits[e]; bi = e; }
            taken[bi] = true;
            topk[r2] = bi;
        }

        float zC = 0.f;
        #pragma unroll
        for (int e = 0; e < NE; e++) { score[e] = __expf(logits[e] - mC); zC += score[e]; }
        const float izC = 1.f / zC;
        float denom = 0.f;
        #pragma unroll
        for (int e = 0; e < NE; e++) {
            score[e] *= izC;
            if (taken[e]) denom += score[e];
        }
        denom = fmaxf(denom, FLT_EPSILON);
        const float inv_d = 1.f / denom;

        if (out_size >= BZ * NE) {
            #pragma unroll
            for (int e = 0; e < NE; e++)
                out[bb * NE + e] = taken[e] ? score[e] * inv_d : 0.f;
        }
        if (out_size >= BZ * NE + BZ * RK) {
            #pragma unroll
            for (int r2 = 0; r2 < RK; r2++)
                out[BZ * NE + bb * RK + r2] = (float)topk[r2];
        }
    }
    __syncthreads();
    if (t == 0) g_count = 0;   // reset for next graph replay
}

extern "C" void kernel_launch(void* const* d_in, const int* in_sizes, int n_in,
                              void* d_out, int out_size) {
    const float* x     = (const float*)d_in[0];
    const int*   idx   = (const int*)  d_in[1];
    const float* W_b   = (const float*)d_in[2];
    const float* embed = (const float*)d_in[3];
    const float* W_c   = (const float*)d_in[4];
    float* out = (float*)d_out;

    dim3 grid(BZ, DCH);
    fused_selector<<<grid, 512>>>(x, idx, W_b, embed, W_c, out, out_size);
}